// round 12
// baseline (speedup 1.0000x reference)
#include <cuda_runtime.h>
#include <cuda_bf16.h>
#include <cstddef>
#include <cstdint>

// ---------------------------------------------------------------------------
// ConvGraphNet (5-layer GCN) on GB300.
// R12: all four big GEMMs (L1-L4) on mma.sync bf16x3; L4 N padded 64->128.
//      Tiled (coalesced) weight transpose; zero-padding fused into producers;
//      dinv fused into scan. CSR gather-reduce aggregation.
// ---------------------------------------------------------------------------

#define NODES_MAX 50000
#define EDGES_MAX 400000
#define MPAD_MAX  50048   // 391 * 128

static __device__ float g_bufA[(size_t)NODES_MAX * 1024];
static __device__ float g_bufB[(size_t)NODES_MAX * 1024];
static __device__ float g_dinv[NODES_MAX];
static __device__ int   g_cnt[NODES_MAX];
static __device__ int   g_rows[NODES_MAX + 1];
static __device__ int   g_pos[NODES_MAX];
static __device__ int   g_partial[256];
static __device__ int   g_csr_src[EDGES_MAX];
static __device__ float g_csr_nrm[EDGES_MAX];
static __device__ __nv_bfloat16 g_wthi[1024 * 512];
static __device__ __nv_bfloat16 g_wtlo[1024 * 512];
static __device__ __nv_bfloat16 g_ahi[(size_t)MPAD_MAX * 512];
static __device__ __nv_bfloat16 g_alo[(size_t)MPAD_MAX * 512];
static __device__ __nv_bfloat16 g_bhi[(size_t)MPAD_MAX * 1024];
static __device__ __nv_bfloat16 g_blo[(size_t)MPAD_MAX * 1024];

// ---------------------------- PTX helpers ----------------------------------

__device__ __forceinline__ uint32_t smem_u32(const void* p) {
    uint32_t a;
    asm("{ .reg .u64 t; cvta.to.shared.u64 t, %1; cvt.u32.u64 %0, t; }"
        : "=r"(a) : "l"(p));
    return a;
}

__device__ __forceinline__ void cpa16(uint32_t s, const void* g) {
    asm volatile("cp.async.cg.shared.global [%0], [%1], 16;" :: "r"(s), "l"(g));
}

__device__ __forceinline__ void ldsm_x4(uint32_t* r, uint32_t addr) {
    asm volatile("ldmatrix.sync.aligned.m8n8.x4.shared.b16 {%0,%1,%2,%3}, [%4];"
                 : "=r"(r[0]), "=r"(r[1]), "=r"(r[2]), "=r"(r[3]) : "r"(addr));
}

__device__ __forceinline__ void mma_bf16(float* d, const uint32_t* a, const uint32_t* b) {
    asm volatile("mma.sync.aligned.m16n8k16.row.col.f32.bf16.bf16.f32 "
                 "{%0,%1,%2,%3}, {%4,%5,%6,%7}, {%8,%9}, {%0,%1,%2,%3};"
                 : "+f"(d[0]), "+f"(d[1]), "+f"(d[2]), "+f"(d[3])
                 : "r"(a[0]), "r"(a[1]), "r"(a[2]), "r"(a[3]), "r"(b[0]), "r"(b[1]));
}

__device__ __forceinline__ void split2(float x, float y, uint32_t& h, uint32_t& l) {
    __nv_bfloat162 hb = __floats2bfloat162_rn(x, y);
    float2 hf = __bfloat1622float2(hb);
    __nv_bfloat162 lb = __floats2bfloat162_rn(x - hf.x, y - hf.y);
    h = *(uint32_t*)&hb;
    l = *(uint32_t*)&lb;
}

// ---------------------------- CSR build ------------------------------------

__global__ void k_zero_cnt(int* __restrict__ cnt, int n) {
    int i = blockIdx.x * blockDim.x + threadIdx.x;
    if (i < n) cnt[i] = 0;
}

__global__ void k_hist(const int* __restrict__ dst, int* __restrict__ cnt, int e) {
    int i = blockIdx.x * blockDim.x + threadIdx.x;
    if (i < e) atomicAdd(&cnt[dst[i]], 1);
}

// scan of cnt -> rows (exclusive, local) + dinv computed on the side
__global__ void k_scan_blk(const int* __restrict__ cnt, int* __restrict__ rows,
                           int* __restrict__ partial, float* __restrict__ dinv, int n) {
    __shared__ int sm[256];
    int t = threadIdx.x;
    int i = blockIdx.x * 256 + t;
    int v = (i < n) ? cnt[i] : 0;
    if (i < n) dinv[i] = rsqrtf((float)(v + 1));
    sm[t] = v;
    __syncthreads();
    #pragma unroll
    for (int off = 1; off < 256; off <<= 1) {
        int x = (t >= off) ? sm[t - off] : 0;
        __syncthreads();
        sm[t] += x;
        __syncthreads();
    }
    if (i < n) rows[i] = sm[t] - v;
    if (t == 255) partial[blockIdx.x] = sm[255];
}

__global__ void k_scan_top(int* __restrict__ partial, int nb) {
    __shared__ int sm[256];
    int t = threadIdx.x;
    int v = (t < nb) ? partial[t] : 0;
    sm[t] = v;
    __syncthreads();
    #pragma unroll
    for (int off = 1; off < 256; off <<= 1) {
        int x = (t >= off) ? sm[t - off] : 0;
        __syncthreads();
        sm[t] += x;
        __syncthreads();
    }
    if (t < nb) partial[t] = sm[t] - v;
}

__global__ void k_scan_add(int* __restrict__ rows, int* __restrict__ pos,
                           const int* __restrict__ partial, int n, int e_total) {
    int i = blockIdx.x * 256 + threadIdx.x;
    if (i < n) {
        int r = rows[i] + partial[blockIdx.x];
        rows[i] = r;
        pos[i] = r;
    }
    if (i == 0) rows[n] = e_total;
}

__global__ void k_scatter(const int* __restrict__ src, const int* __restrict__ dst,
                          const float* __restrict__ dinv, int* __restrict__ pos,
                          int* __restrict__ csr_src, float* __restrict__ csr_nrm, int e) {
    int i = blockIdx.x * blockDim.x + threadIdx.x;
    if (i >= e) return;
    int s = src[i], d = dst[i];
    int j = atomicAdd(&pos[d], 1);
    csr_src[j] = s;
    csr_nrm[j] = dinv[s] * dinv[d];
}

// ---------------------------- CSR aggregation -------------------------------

// fp32-out version
template <int F4PN>
__global__ __launch_bounds__(256)
void k_csr_agg(const float4* __restrict__ X, const int* __restrict__ rows,
               const int* __restrict__ csr_src, const float* __restrict__ csr_nrm,
               const float* __restrict__ dinv, const float* __restrict__ bias,
               float4* __restrict__ out, int n) {
    const int NPB = 256 / F4PN;
    int tid = threadIdx.x;
    int local = tid / F4PN;
    int f4 = tid % F4PN;
    int i = blockIdx.x * NPB + local;
    if (i >= n) return;

    float d = dinv[i];
    float s = d * d;
    size_t base = (size_t)i * F4PN + f4;
    float4 xs = X[base];
    float4 acc;
    acc.x = xs.x * s; acc.y = xs.y * s; acc.z = xs.z * s; acc.w = xs.w * s;
    if (bias) {
        float4 b = ((const float4*)bias)[f4];
        acc.x += b.x; acc.y += b.y; acc.z += b.z; acc.w += b.w;
    }
    int beg = rows[i], end = rows[i + 1];
    for (int j = beg; j < end; j++) {
        float w = csr_nrm[j];
        float4 v = X[(size_t)csr_src[j] * F4PN + f4];
        acc.x = fmaf(w, v.x, acc.x);
        acc.y = fmaf(w, v.y, acc.y);
        acc.z = fmaf(w, v.z, acc.z);
        acc.w = fmaf(w, v.w, acc.w);
    }
    out[base] = acc;
}

// bf16 hi/lo-out version; grid covers npad nodes, pad rows -> zeros.
template <int F4PN, int RELU>
__global__ __launch_bounds__(256)
void k_csr_agg_split(const float4* __restrict__ X, const int* __restrict__ rows,
                     const int* __restrict__ csr_src, const float* __restrict__ csr_nrm,
                     const float* __restrict__ dinv, const float* __restrict__ bias,
                     uint2* __restrict__ hi, uint2* __restrict__ lo, int n, int npad) {
    const int NPB = 256 / F4PN;
    int tid = threadIdx.x;
    int local = tid / F4PN;
    int f4 = tid % F4PN;
    int i = blockIdx.x * NPB + local;
    if (i >= npad) return;
    size_t base = (size_t)i * F4PN + f4;
    if (i >= n) {
        hi[base] = make_uint2(0, 0);
        lo[base] = make_uint2(0, 0);
        return;
    }

    float d = dinv[i];
    float s = d * d;
    float4 xs = X[base];
    float4 acc;
    acc.x = xs.x * s; acc.y = xs.y * s; acc.z = xs.z * s; acc.w = xs.w * s;
    if (bias) {
        float4 b = ((const float4*)bias)[f4];
        acc.x += b.x; acc.y += b.y; acc.z += b.z; acc.w += b.w;
    }
    int beg = rows[i], end = rows[i + 1];
    for (int j = beg; j < end; j++) {
        float w = csr_nrm[j];
        float4 v = X[(size_t)csr_src[j] * F4PN + f4];
        acc.x = fmaf(w, v.x, acc.x);
        acc.y = fmaf(w, v.y, acc.y);
        acc.z = fmaf(w, v.z, acc.z);
        acc.w = fmaf(w, v.w, acc.w);
    }
    if (RELU) {
        acc.x = fmaxf(acc.x, 0.f); acc.y = fmaxf(acc.y, 0.f);
        acc.z = fmaxf(acc.z, 0.f); acc.w = fmaxf(acc.w, 0.f);
    }
    uint2 uh, ul;
    split2(acc.x, acc.y, uh.x, ul.x);
    split2(acc.z, acc.w, uh.y, ul.y);
    hi[base] = uh;
    lo[base] = ul;
}

__global__ void k_out_scalar(const float* __restrict__ mv, const int* __restrict__ rows,
                             const int* __restrict__ csr_src, const float* __restrict__ csr_nrm,
                             const float* __restrict__ dinv, const float* __restrict__ b5,
                             float* __restrict__ out, int n) {
    int i = blockIdx.x * blockDim.x + threadIdx.x;
    if (i >= n) return;
    float d = dinv[i];
    float s = b5[0] + d * d * mv[i];
    int beg = rows[i], end = rows[i + 1];
    for (int j = beg; j < end; j++)
        s = fmaf(csr_nrm[j], mv[csr_src[j]], s);
    out[i] = fmaxf(s, 0.0f);
}

// ---------------- tiled weight transpose + bf16 split -----------------------
// W[k][n] (row-major KxNvalid) -> hi/lo[n][k] for n < Npad (zero for
// n >= Nvalid). Coalesced both sides via 32x32 smem tile. Block (32,8),
// grid (K/32, Npad/32).

__global__ __launch_bounds__(256)
void k_wt_t(const float* __restrict__ W, __nv_bfloat16* __restrict__ hi,
            __nv_bfloat16* __restrict__ lo, int K, int Nvalid) {
    __shared__ float tile[32][33];
    int k0 = blockIdx.x * 32;
    int n0 = blockIdx.y * 32;
    int tx = threadIdx.x, ty = threadIdx.y;
    #pragma unroll
    for (int i = ty; i < 32; i += 8) {
        int k = k0 + i, n = n0 + tx;
        tile[i][tx] = (n < Nvalid) ? W[(size_t)k * Nvalid + n] : 0.0f;
    }
    __syncthreads();
    #pragma unroll
    for (int i = ty; i < 32; i += 8) {
        int n = n0 + i, k = k0 + tx;
        float v = tile[tx][i];
        __nv_bfloat16 h = __float2bfloat16(v);
        hi[(size_t)n * K + k] = h;
        lo[(size_t)n * K + k] = __float2bfloat16(v - __bfloat162float(h));
    }
}

// ---------------------- mma.sync bf16x3 GEMM --------------------------------
// C = A @ W; A bf16 hi/lo [Mpad,K] row-major; W bf16 hi/lo [Ncols][K] K-major
// (Ncols = gridDim.x*128). Block 128x128, 8 warps (4m x 2n), warp 32x64,
// BK=64, 2-stage cp.async.
// mode 0: fp32 out, row stride Nout, only cols < Nout stored.
// mode 2: bf16 hi/lo out (bias+relu); pad rows [M, Mpad) zeroed.

#define SROW 144
#define SARR (128 * SROW)
#define SSTAGE (4 * SARR)
#define MMA_SMEM (2 * SSTAGE)

__global__ __launch_bounds__(256, 1)
void k_mma_gemm(const __nv_bfloat16* __restrict__ Ah, const __nv_bfloat16* __restrict__ Al,
                const __nv_bfloat16* __restrict__ Bh, const __nv_bfloat16* __restrict__ Bl,
                const float* __restrict__ bias, float* __restrict__ C,
                __nv_bfloat16* __restrict__ Chi, __nv_bfloat16* __restrict__ Clo,
                int M, int K, int Nout, int mode) {
    extern __shared__ char smem[];
    const uint32_t sb = smem_u32(smem);
    const int tid = threadIdx.x;
    const int wid = tid >> 5;
    const int lane = tid & 31;
    const int warp_m = wid & 3;
    const int warp_n = wid >> 2;
    const int row0 = blockIdx.y * 128;
    const int col0 = blockIdx.x * 128;
    const int nc = K >> 6;

    const uint32_t offAh = 0, offAl = SARR, offBh = 2 * SARR, offBl = 3 * SARR;

    float acc[2][8][4];
    #pragma unroll
    for (int i = 0; i < 2; i++)
        #pragma unroll
        for (int j = 0; j < 8; j++)
            #pragma unroll
            for (int c = 0; c < 4; c++) acc[i][j][c] = 0.0f;

    auto issue = [&](int t, int q) {
        size_t k0 = (size_t)t << 6;
        uint32_t st = sb + q * SSTAGE;
        #pragma unroll
        for (int l = 0; l < 4; l++) {
            int idx = tid + l * 256;
            int r = idx >> 3;
            int c = idx & 7;
            uint32_t o = (uint32_t)(r * SROW + c * 16);
            size_t ga = (size_t)(row0 + r) * K + k0 + c * 8;
            size_t gb = (size_t)(col0 + r) * K + k0 + c * 8;
            cpa16(st + offAh + o, Ah + ga);
            cpa16(st + offAl + o, Al + ga);
            cpa16(st + offBh + o, Bh + gb);
            cpa16(st + offBl + o, Bl + gb);
        }
        asm volatile("cp.async.commit_group;" ::: "memory");
    };

    issue(0, 0);

    for (int t = 0; t < nc; t++) {
        int p = t & 1;
        if (t + 1 < nc) {
            issue(t + 1, (t + 1) & 1);
            asm volatile("cp.async.wait_group 1;" ::: "memory");
        } else {
            asm volatile("cp.async.wait_group 0;" ::: "memory");
        }
        __syncthreads();

        uint32_t st = sb + p * SSTAGE;
        #pragma unroll
        for (int ks = 0; ks < 4; ks++) {
            uint32_t ah[2][4], al[2][4];
            {
                uint32_t rr = (uint32_t)(warp_m * 32 + (lane & 15));
                uint32_t cc = (uint32_t)(ks * 16 + ((lane >> 4) << 3));
                #pragma unroll
                for (int mt = 0; mt < 2; mt++) {
                    uint32_t o = (rr + mt * 16) * SROW + cc * 2;
                    ldsm_x4(ah[mt], st + offAh + o);
                    ldsm_x4(al[mt], st + offAl + o);
                }
            }
            uint32_t bh[4][4], bl[4][4];
            {
                int j = lane >> 3;
                uint32_t nn = (uint32_t)(warp_n * 64 + ((j >> 1) << 3) + (lane & 7));
                uint32_t kk = (uint32_t)(ks * 16 + ((j & 1) << 3));
                #pragma unroll
                for (int pp = 0; pp < 4; pp++) {
                    uint32_t o = (nn + pp * 16) * SROW + kk * 2;
                    ldsm_x4(bh[pp], st + offBh + o);
                    ldsm_x4(bl[pp], st + offBl + o);
                }
            }
            #pragma unroll
            for (int mt = 0; mt < 2; mt++)
                #pragma unroll
                for (int nt = 0; nt < 8; nt++) {
                    const uint32_t* Bhf = &bh[nt >> 1][(nt & 1) * 2];
                    const uint32_t* Blf = &bl[nt >> 1][(nt & 1) * 2];
                    mma_bf16(acc[mt][nt], ah[mt], Bhf);
                    mma_bf16(acc[mt][nt], ah[mt], Blf);
                    mma_bf16(acc[mt][nt], al[mt], Bhf);
                }
        }
        __syncthreads();
    }

    // ---- epilogue ----
    int gid = lane >> 2, tig = lane & 3;
    #pragma unroll
    for (int mt = 0; mt < 2; mt++) {
        int r0 = row0 + warp_m * 32 + mt * 16 + gid;
        #pragma unroll
        for (int nt = 0; nt < 8; nt++) {
            int cc = col0 + warp_n * 64 + nt * 8 + tig * 2;
            float2 v0 = make_float2(acc[mt][nt][0], acc[mt][nt][1]);
            float2 v1 = make_float2(acc[mt][nt][2], acc[mt][nt][3]);
            if (mode == 2) {
                float bx = bias[cc], by = bias[cc + 1];
                v0.x = fmaxf(v0.x + bx, 0.f); v0.y = fmaxf(v0.y + by, 0.f);
                v1.x = fmaxf(v1.x + bx, 0.f); v1.y = fmaxf(v1.y + by, 0.f);
                uint32_t h0, l0, h1, l1;
                split2(v0.x, v0.y, h0, l0);
                split2(v1.x, v1.y, h1, l1);
                if (r0 >= M) { h0 = l0 = 0; }
                if (r0 + 8 >= M) { h1 = l1 = 0; }
                *(uint32_t*)&Chi[(size_t)r0 * Nout + cc] = h0;
                *(uint32_t*)&Clo[(size_t)r0 * Nout + cc] = l0;
                *(uint32_t*)&Chi[(size_t)(r0 + 8) * Nout + cc] = h1;
                *(uint32_t*)&Clo[(size_t)(r0 + 8) * Nout + cc] = l1;
            } else {
                if (cc < Nout) {
                    if (r0 < M)     *(float2*)&C[(size_t)r0 * Nout + cc] = v0;
                    if (r0 + 8 < M) *(float2*)&C[(size_t)(r0 + 8) * Nout + cc] = v1;
                }
            }
        }
    }
}

// L5 matvec
__global__ void k_matvec64(const float* __restrict__ X, const float* __restrict__ W,
                           float* __restrict__ out, int M) {
    __shared__ float w[64];
    int t = threadIdx.x;
    if (t < 64) w[t] = W[t];
    __syncthreads();
    int i = blockIdx.x * blockDim.x + t;
    if (i < M) {
        const float4* xr = (const float4*)(X + (size_t)i * 64);
        float s = 0.f;
        #pragma unroll
        for (int k = 0; k < 16; k++) {
            float4 v = xr[k];
            s = fmaf(fmaxf(v.x, 0.f), w[4 * k + 0], s);
            s = fmaf(fmaxf(v.y, 0.f), w[4 * k + 1], s);
            s = fmaf(fmaxf(v.z, 0.f), w[4 * k + 2], s);
            s = fmaf(fmaxf(v.w, 0.f), w[4 * k + 3], s);
        }
        out[i] = s;
    }
}

// ---------------------------- launch ---------------------------------------

static inline unsigned blocks_for(size_t total, int threads) {
    return (unsigned)((total + threads - 1) / threads);
}

extern "C" void kernel_launch(void* const* d_in, const int* in_sizes, int n_in,
                              void* d_out, int out_size) {
    const float* x  = (const float*)d_in[0];
    const int*   ei = (const int*)d_in[1];
    const int N = in_sizes[0] / 128;
    const int E = in_sizes[1] / 2;
    const int* src = ei;
    const int* dst = ei + E;
    const float* W1 = (const float*)d_in[2];  const float* b1 = (const float*)d_in[3];
    const float* W2 = (const float*)d_in[4];  const float* b2 = (const float*)d_in[5];
    const float* W3 = (const float*)d_in[6];  const float* b3 = (const float*)d_in[7];
    const float* W4 = (const float*)d_in[8];  const float* b4 = (const float*)d_in[9];
    const float* W5 = (const float*)d_in[10]; const float* b5 = (const float*)d_in[11];
    float* out = (float*)d_out;

    float *bufA, *bufB, *dinv, *csr_nrm;
    int *cnt, *rows, *pos, *partial, *csr_src;
    __nv_bfloat16 *wthi, *wtlo, *ahi, *alo, *bhi, *blo;
    cudaGetSymbolAddress((void**)&bufA, g_bufA);
    cudaGetSymbolAddress((void**)&bufB, g_bufB);
    cudaGetSymbolAddress((void**)&dinv, g_dinv);
    cudaGetSymbolAddress((void**)&cnt, g_cnt);
    cudaGetSymbolAddress((void**)&rows, g_rows);
    cudaGetSymbolAddress((void**)&pos, g_pos);
    cudaGetSymbolAddress((void**)&partial, g_partial);
    cudaGetSymbolAddress((void**)&csr_src, g_csr_src);
    cudaGetSymbolAddress((void**)&csr_nrm, g_csr_nrm);
    cudaGetSymbolAddress((void**)&wthi, g_wthi);
    cudaGetSymbolAddress((void**)&wtlo, g_wtlo);
    cudaGetSymbolAddress((void**)&ahi, g_ahi);
    cudaGetSymbolAddress((void**)&alo, g_alo);
    cudaGetSymbolAddress((void**)&bhi, g_bhi);
    cudaGetSymbolAddress((void**)&blo, g_blo);

    cudaFuncSetAttribute(k_mma_gemm, cudaFuncAttributeMaxDynamicSharedMemorySize,
                         MMA_SMEM);

    const int T = 256;
    const int nblk = (N + 255) / 256;
    const int mtiles = (N + 127) / 128;
    const int Mpad = mtiles * 128;

    // ---- CSR build ----
    k_zero_cnt<<<nblk, T>>>(cnt, N);
    k_hist<<<blocks_for(E, T), T>>>(dst, cnt, E);
    k_scan_blk<<<nblk, T>>>(cnt, rows, partial, dinv, N);
    k_scan_top<<<1, T>>>(partial, nblk);
    k_scan_add<<<nblk, T>>>(rows, pos, partial, N, E);
    k_scatter<<<blocks_for(E, T), T>>>(src, dst, dinv, pos, csr_src, csr_nrm, E);

    // ---- Layer 1: CSR-agg of x -> ahi/alo [*,128] (pad fused);
    //      GEMM 128->1024 (b1+relu) -> bhi/blo (pad fused) ----
    k_csr_agg_split<32, 0><<<(Mpad + 7) / 8, 256>>>(
        (const float4*)x, rows, csr_src, csr_nrm, dinv, nullptr,
        (uint2*)ahi, (uint2*)alo, N, Mpad);
    k_wt_t<<<dim3(128 / 32, 1024 / 32), dim3(32, 8)>>>(W1, wthi, wtlo, 128, 1024);
    k_mma_gemm<<<dim3(1024 / 128, mtiles), 256, MMA_SMEM>>>(
        ahi, alo, wthi, wtlo, b1, nullptr, bhi, blo, N, 128, 1024, 2);

    // ---- Layer 2: GEMM 1024->512 -> bufA; CSR-agg (+b2, relu) -> ahi/alo ----
    k_wt_t<<<dim3(1024 / 32, 512 / 32), dim3(32, 8)>>>(W2, wthi, wtlo, 1024, 512);
    k_mma_gemm<<<dim3(512 / 128, mtiles), 256, MMA_SMEM>>>(
        bhi, blo, wthi, wtlo, nullptr, bufA, nullptr, nullptr, N, 1024, 512, 0);
    k_csr_agg_split<128, 1><<<(Mpad + 1) / 2, 256>>>(
        (const float4*)bufA, rows, csr_src, csr_nrm, dinv, b2,
        (uint2*)ahi, (uint2*)alo, N, Mpad);

    // ---- Layer 3: GEMM 512->256 -> bufA; CSR-agg (+b3, relu) -> ahi/alo ----
    k_wt_t<<<dim3(512 / 32, 256 / 32), dim3(32, 8)>>>(W3, wthi, wtlo, 512, 256);
    k_mma_gemm<<<dim3(256 / 128, mtiles), 256, MMA_SMEM>>>(
        ahi, alo, wthi, wtlo, nullptr, bufA, nullptr, nullptr, N, 512, 256, 0);
    k_csr_agg_split<64, 1><<<(Mpad + 3) / 4, 256>>>(
        (const float4*)bufA, rows, csr_src, csr_nrm, dinv, b3,
        (uint2*)ahi, (uint2*)alo, N, Mpad);

    // ---- Layer 4: mma GEMM 256->64 (N padded to 128, Nout=64) -> bufA;
    //      CSR-agg (+b4) -> bufB ----
    k_wt_t<<<dim3(256 / 32, 128 / 32), dim3(32, 8)>>>(W4, wthi, wtlo, 256, 64);
    k_mma_gemm<<<dim3(1, mtiles), 256, MMA_SMEM>>>(
        ahi, alo, wthi, wtlo, nullptr, bufA, nullptr, nullptr, N, 256, 64, 0);
    k_csr_agg<16><<<(N + 15) / 16, 256>>>((const float4*)bufA, rows, csr_src, csr_nrm,
                                          dinv, b4, (float4*)bufB, N);

    // ---- Layer 5: matvec 64->1 (relu in), scalar CSR-agg into out ----
    k_matvec64<<<blocks_for(N, T), T>>>(bufB, W5, bufA, N);
    k_out_scalar<<<nblk, T>>>(bufA, rows, csr_src, csr_nrm, dinv, b5, out, N);
}

// round 13
// speedup vs baseline: 1.0261x; 1.0261x over previous
#include <cuda_runtime.h>
#include <cuda_bf16.h>
#include <cstddef>
#include <cstdint>

// ---------------------------------------------------------------------------
// ConvGraphNet (5-layer GCN) on GB300.
// R13: mma.sync bf16x3 GEMMs with 3-stage cp.async pipeline (single barrier
//      per K-chunk, issue after barrier); L5 matvec fused into L4 CSR-agg;
//      CSR build slimmed to 4 launches; one batched weight-transpose launch.
// ---------------------------------------------------------------------------

#define NODES_MAX 50000
#define EDGES_MAX 400000
#define MPAD_MAX  50048   // 391 * 128

static __device__ float g_bufA[(size_t)NODES_MAX * 1024];
static __device__ float g_bufB[(size_t)NODES_MAX * 1024];
static __device__ float g_dinv[NODES_MAX];
static __device__ int   g_cnt[NODES_MAX];
static __device__ int   g_rows[NODES_MAX + 1];
static __device__ int   g_pos[NODES_MAX];
static __device__ int   g_partial[256];
static __device__ int   g_csr_src[EDGES_MAX];
static __device__ float g_csr_nrm[EDGES_MAX];
static __device__ __nv_bfloat16 g_wthi[1 << 20];
static __device__ __nv_bfloat16 g_wtlo[1 << 20];
static __device__ __nv_bfloat16 g_ahi[(size_t)MPAD_MAX * 512];
static __device__ __nv_bfloat16 g_alo[(size_t)MPAD_MAX * 512];
static __device__ __nv_bfloat16 g_bhi[(size_t)MPAD_MAX * 1024];
static __device__ __nv_bfloat16 g_blo[(size_t)MPAD_MAX * 1024];

// weight-transpose regions inside g_wthi/g_wtlo
#define WOFF1 0          // W1t: 1024 x 128
#define WOFF2 131072     // W2t: 512 x 1024
#define WOFF3 655360     // W3t: 256 x 512
#define WOFF4 786432     // W4t: 128 x 256 (cols 64..127 zero)

// ---------------------------- PTX helpers ----------------------------------

__device__ __forceinline__ uint32_t smem_u32(const void* p) {
    uint32_t a;
    asm("{ .reg .u64 t; cvta.to.shared.u64 t, %1; cvt.u32.u64 %0, t; }"
        : "=r"(a) : "l"(p));
    return a;
}

__device__ __forceinline__ void cpa16(uint32_t s, const void* g) {
    asm volatile("cp.async.cg.shared.global [%0], [%1], 16;" :: "r"(s), "l"(g));
}

__device__ __forceinline__ void ldsm_x4(uint32_t* r, uint32_t addr) {
    asm volatile("ldmatrix.sync.aligned.m8n8.x4.shared.b16 {%0,%1,%2,%3}, [%4];"
                 : "=r"(r[0]), "=r"(r[1]), "=r"(r[2]), "=r"(r[3]) : "r"(addr));
}

__device__ __forceinline__ void mma_bf16(float* d, const uint32_t* a, const uint32_t* b) {
    asm volatile("mma.sync.aligned.m16n8k16.row.col.f32.bf16.bf16.f32 "
                 "{%0,%1,%2,%3}, {%4,%5,%6,%7}, {%8,%9}, {%0,%1,%2,%3};"
                 : "+f"(d[0]), "+f"(d[1]), "+f"(d[2]), "+f"(d[3])
                 : "r"(a[0]), "r"(a[1]), "r"(a[2]), "r"(a[3]), "r"(b[0]), "r"(b[1]));
}

__device__ __forceinline__ void split2(float x, float y, uint32_t& h, uint32_t& l) {
    __nv_bfloat162 hb = __floats2bfloat162_rn(x, y);
    float2 hf = __bfloat1622float2(hb);
    __nv_bfloat162 lb = __floats2bfloat162_rn(x - hf.x, y - hf.y);
    h = *(uint32_t*)&hb;
    l = *(uint32_t*)&lb;
}

// ---------------------------- CSR build ------------------------------------
// cnt is zeroed at the END of k_scan_add2 each call (static init covers the
// first call), so no standalone zero pass is needed.

__global__ void k_hist(const int* __restrict__ dst, int* __restrict__ cnt, int e) {
    int i = blockIdx.x * blockDim.x + threadIdx.x;
    if (i < e) atomicAdd(&cnt[dst[i]], 1);
}

// block-local exclusive scan of cnt -> rows + block sums -> partial; dinv too
__global__ void k_scan_blk(const int* __restrict__ cnt, int* __restrict__ rows,
                           int* __restrict__ partial, float* __restrict__ dinv, int n) {
    __shared__ int sm[256];
    int t = threadIdx.x;
    int i = blockIdx.x * 256 + t;
    int v = (i < n) ? cnt[i] : 0;
    if (i < n) dinv[i] = rsqrtf((float)(v + 1));
    sm[t] = v;
    __syncthreads();
    #pragma unroll
    for (int off = 1; off < 256; off <<= 1) {
        int x = (t >= off) ? sm[t - off] : 0;
        __syncthreads();
        sm[t] += x;
        __syncthreads();
    }
    if (i < n) rows[i] = sm[t] - v;
    if (t == 255) partial[blockIdx.x] = sm[255];
}

// finalize rows/pos (adding prefix of partials computed per-block) + zero cnt
__global__ void k_scan_add2(int* __restrict__ rows, int* __restrict__ pos,
                            const int* __restrict__ partial, int* __restrict__ cnt,
                            int n, int e_total) {
    __shared__ int sm[256];
    int t = threadIdx.x;
    int bid = blockIdx.x;
    sm[t] = (t < bid) ? partial[t] : 0;   // gridDim.x <= 256
    __syncthreads();
    #pragma unroll
    for (int off = 128; off >= 1; off >>= 1) {
        if (t < off) sm[t] += sm[t + off];
        __syncthreads();
    }
    int offv = sm[0];
    int i = bid * 256 + t;
    if (i < n) {
        int r = rows[i] + offv;
        rows[i] = r;
        pos[i] = r;
        cnt[i] = 0;     // ready for next call's k_hist
    }
    if (i == 0) rows[n] = e_total;
}

__global__ void k_scatter(const int* __restrict__ src, const int* __restrict__ dst,
                          const float* __restrict__ dinv, int* __restrict__ pos,
                          int* __restrict__ csr_src, float* __restrict__ csr_nrm, int e) {
    int i = blockIdx.x * blockDim.x + threadIdx.x;
    if (i >= e) return;
    int s = src[i], d = dst[i];
    int j = atomicAdd(&pos[d], 1);
    csr_src[j] = s;
    csr_nrm[j] = dinv[s] * dinv[d];
}

// ---------------------------- CSR aggregation -------------------------------

// bf16 hi/lo-out version; grid covers npad nodes, pad rows -> zeros.
template <int F4PN, int RELU>
__global__ __launch_bounds__(256)
void k_csr_agg_split(const float4* __restrict__ X, const int* __restrict__ rows,
                     const int* __restrict__ csr_src, const float* __restrict__ csr_nrm,
                     const float* __restrict__ dinv, const float* __restrict__ bias,
                     uint2* __restrict__ hi, uint2* __restrict__ lo, int n, int npad) {
    const int NPB = 256 / F4PN;
    int tid = threadIdx.x;
    int local = tid / F4PN;
    int f4 = tid % F4PN;
    int i = blockIdx.x * NPB + local;
    if (i >= npad) return;
    size_t base = (size_t)i * F4PN + f4;
    if (i >= n) {
        hi[base] = make_uint2(0, 0);
        lo[base] = make_uint2(0, 0);
        return;
    }

    float d = dinv[i];
    float s = d * d;
    float4 xs = X[base];
    float4 acc;
    acc.x = xs.x * s; acc.y = xs.y * s; acc.z = xs.z * s; acc.w = xs.w * s;
    if (bias) {
        float4 b = ((const float4*)bias)[f4];
        acc.x += b.x; acc.y += b.y; acc.z += b.z; acc.w += b.w;
    }
    int beg = rows[i], end = rows[i + 1];
    for (int j = beg; j < end; j++) {
        float w = csr_nrm[j];
        float4 v = X[(size_t)csr_src[j] * F4PN + f4];
        acc.x = fmaf(w, v.x, acc.x);
        acc.y = fmaf(w, v.y, acc.y);
        acc.z = fmaf(w, v.z, acc.z);
        acc.w = fmaf(w, v.w, acc.w);
    }
    if (RELU) {
        acc.x = fmaxf(acc.x, 0.f); acc.y = fmaxf(acc.y, 0.f);
        acc.z = fmaxf(acc.z, 0.f); acc.w = fmaxf(acc.w, 0.f);
    }
    uint2 uh, ul;
    split2(acc.x, acc.y, uh.x, ul.x);
    split2(acc.z, acc.w, uh.y, ul.y);
    hi[base] = uh;
    lo[base] = ul;
}

// L4 aggregation (F=64, +b4) fused with relu + W5 matvec -> mv[i] (scalar).
__global__ __launch_bounds__(256)
void k_csr_agg_mv(const float4* __restrict__ X, const int* __restrict__ rows,
                  const int* __restrict__ csr_src, const float* __restrict__ csr_nrm,
                  const float* __restrict__ dinv, const float* __restrict__ b4,
                  const float* __restrict__ W5, float* __restrict__ mv, int n) {
    int tid = threadIdx.x;
    int local = tid >> 4;        // 16 nodes / block
    int f4 = tid & 15;           // 16 float4 lanes = 64 feats
    int i = blockIdx.x * 16 + local;
    bool valid = (i < n);
    int ii = valid ? i : 0;

    float d = dinv[ii];
    float s = d * d;
    size_t base = (size_t)ii * 16 + f4;
    float4 xs = X[base];
    float4 b = ((const float4*)b4)[f4];
    float4 acc;
    acc.x = fmaf(xs.x, s, b.x); acc.y = fmaf(xs.y, s, b.y);
    acc.z = fmaf(xs.z, s, b.z); acc.w = fmaf(xs.w, s, b.w);
    int beg = rows[ii], end = valid ? rows[ii + 1] : rows[ii];
    for (int j = beg; j < end; j++) {
        float w = csr_nrm[j];
        float4 v = X[(size_t)csr_src[j] * 16 + f4];
        acc.x = fmaf(w, v.x, acc.x);
        acc.y = fmaf(w, v.y, acc.y);
        acc.z = fmaf(w, v.z, acc.z);
        acc.w = fmaf(w, v.w, acc.w);
    }
    float4 w5 = ((const float4*)W5)[f4];
    float p = fmaxf(acc.x, 0.f) * w5.x + fmaxf(acc.y, 0.f) * w5.y +
              fmaxf(acc.z, 0.f) * w5.z + fmaxf(acc.w, 0.f) * w5.w;
    p += __shfl_xor_sync(0xffffffffu, p, 8, 16);
    p += __shfl_xor_sync(0xffffffffu, p, 4, 16);
    p += __shfl_xor_sync(0xffffffffu, p, 2, 16);
    p += __shfl_xor_sync(0xffffffffu, p, 1, 16);
    if (valid && f4 == 0) mv[i] = p;
}

__global__ void k_out_scalar(const float* __restrict__ mv, const int* __restrict__ rows,
                             const int* __restrict__ csr_src, const float* __restrict__ csr_nrm,
                             const float* __restrict__ dinv, const float* __restrict__ b5,
                             float* __restrict__ out, int n) {
    int i = blockIdx.x * blockDim.x + threadIdx.x;
    if (i >= n) return;
    float d = dinv[i];
    float s = b5[0] + d * d * mv[i];
    int beg = rows[i], end = rows[i + 1];
    for (int j = beg; j < end; j++)
        s = fmaf(csr_nrm[j], mv[csr_src[j]], s);
    out[i] = fmaxf(s, 0.0f);
}

// ---------------- batched tiled weight transpose + bf16 split ---------------
// blockIdx.z selects which weight; W[k][n] -> hi/lo[off + n*K + k],
// n in [0,Npad), zeros for n >= Nvalid. 32x32 smem tile, coalesced both ways.

__global__ __launch_bounds__(256)
void k_wt_all(const float* __restrict__ W1, const float* __restrict__ W2,
              const float* __restrict__ W3, const float* __restrict__ W4,
              __nv_bfloat16* __restrict__ hi, __nv_bfloat16* __restrict__ lo) {
    __shared__ float tile[32][33];
    const float* W;
    int K, Nv, Npad;
    size_t off;
    switch (blockIdx.z) {
        case 0:  W = W1; K = 128;  Nv = 1024; Npad = 1024; off = WOFF1; break;
        case 1:  W = W2; K = 1024; Nv = 512;  Npad = 512;  off = WOFF2; break;
        case 2:  W = W3; K = 512;  Nv = 256;  Npad = 256;  off = WOFF3; break;
        default: W = W4; K = 256;  Nv = 64;   Npad = 128;  off = WOFF4; break;
    }
    int k0 = blockIdx.x * 32;
    int n0 = blockIdx.y * 32;
    if (k0 >= K || n0 >= Npad) return;
    int tx = threadIdx.x, ty = threadIdx.y;
    #pragma unroll
    for (int i = ty; i < 32; i += 8) {
        int k = k0 + i, n = n0 + tx;
        tile[i][tx] = (n < Nv) ? W[(size_t)k * Nv + n] : 0.0f;
    }
    __syncthreads();
    #pragma unroll
    for (int i = ty; i < 32; i += 8) {
        int n = n0 + i, k = k0 + tx;
        float v = tile[tx][i];
        __nv_bfloat16 h = __float2bfloat16(v);
        hi[off + (size_t)n * K + k] = h;
        lo[off + (size_t)n * K + k] = __float2bfloat16(v - __bfloat162float(h));
    }
}

// ---------------------- mma.sync bf16x3 GEMM --------------------------------
// C = A @ W; A bf16 hi/lo [Mpad,K] row-major; W bf16 hi/lo [Ncols][K] K-major.
// Block 128x128, 8 warps (4m x 2n), warp 32x64, BK=64,
// 3-stage cp.async pipeline, ONE __syncthreads per chunk (issue after barrier).
// mode 0: fp32 out (row stride Nout, cols < Nout stored).
// mode 2: bf16 hi/lo out (bias+relu); pad rows [M, Mpad) zeroed.

#define SROW 144
#define SARR (128 * SROW)
#define SSTAGE (4 * SARR)          // 73728
#define MMA_SMEM (3 * SSTAGE)      // 221184

__global__ __launch_bounds__(256, 1)
void k_mma_gemm(const __nv_bfloat16* __restrict__ Ah, const __nv_bfloat16* __restrict__ Al,
                const __nv_bfloat16* __restrict__ Bh, const __nv_bfloat16* __restrict__ Bl,
                const float* __restrict__ bias, float* __restrict__ C,
                __nv_bfloat16* __restrict__ Chi, __nv_bfloat16* __restrict__ Clo,
                int M, int K, int Nout, int mode) {
    extern __shared__ char smem[];
    const uint32_t sb = smem_u32(smem);
    const int tid = threadIdx.x;
    const int wid = tid >> 5;
    const int lane = tid & 31;
    const int warp_m = wid & 3;
    const int warp_n = wid >> 2;
    const int row0 = blockIdx.y * 128;
    const int col0 = blockIdx.x * 128;
    const int nc = K >> 6;

    const uint32_t offAh = 0, offAl = SARR, offBh = 2 * SARR, offBl = 3 * SARR;

    float acc[2][8][4];
    #pragma unroll
    for (int i = 0; i < 2; i++)
        #pragma unroll
        for (int j = 0; j < 8; j++)
            #pragma unroll
            for (int c = 0; c < 4; c++) acc[i][j][c] = 0.0f;

    auto issue = [&](int t, int q) {
        size_t k0 = (size_t)t << 6;
        uint32_t st = sb + q * SSTAGE;
        #pragma unroll
        for (int l = 0; l < 4; l++) {
            int idx = tid + l * 256;
            int r = idx >> 3;
            int c = idx & 7;
            uint32_t o = (uint32_t)(r * SROW + c * 16);
            size_t ga = (size_t)(row0 + r) * K + k0 + c * 8;
            size_t gb = (size_t)(col0 + r) * K + k0 + c * 8;
            cpa16(st + offAh + o, Ah + ga);
            cpa16(st + offAl + o, Al + ga);
            cpa16(st + offBh + o, Bh + gb);
            cpa16(st + offBl + o, Bl + gb);
        }
        asm volatile("cp.async.commit_group;" ::: "memory");
    };

    issue(0, 0);
    if (nc > 1) issue(1, 1);

    int buf = 0;
    for (int t = 0; t < nc; t++) {
        if (t + 1 < nc) {
            asm volatile("cp.async.wait_group 1;" ::: "memory");
        } else {
            asm volatile("cp.async.wait_group 0;" ::: "memory");
        }
        __syncthreads();   // chunk t visible; all warps done with chunk t-1
        if (t + 2 < nc) {
            int q = (t + 2) % 3;   // buffer last read at iter t-1 -> safe now
            issue(t + 2, q);
        }

        uint32_t st = sb + buf * SSTAGE;
        #pragma unroll
        for (int ks = 0; ks < 4; ks++) {
            uint32_t ah[2][4], al[2][4];
            {
                uint32_t rr = (uint32_t)(warp_m * 32 + (lane & 15));
                uint32_t cc = (uint32_t)(ks * 16 + ((lane >> 4) << 3));
                #pragma unroll
                for (int mt = 0; mt < 2; mt++) {
                    uint32_t o = (rr + mt * 16) * SROW + cc * 2;
                    ldsm_x4(ah[mt], st + offAh + o);
                    ldsm_x4(al[mt], st + offAl + o);
                }
            }
            uint32_t bh[4][4], bl[4][4];
            {
                int j = lane >> 3;
                uint32_t nn = (uint32_t)(warp_n * 64 + ((j >> 1) << 3) + (lane & 7));
                uint32_t kk = (uint32_t)(ks * 16 + ((j & 1) << 3));
                #pragma unroll
                for (int pp = 0; pp < 4; pp++) {
                    uint32_t o = (nn + pp * 16) * SROW + kk * 2;
                    ldsm_x4(bh[pp], st + offBh + o);
                    ldsm_x4(bl[pp], st + offBl + o);
                }
            }
            #pragma unroll
            for (int mt = 0; mt < 2; mt++)
                #pragma unroll
                for (int nt = 0; nt < 8; nt++) {
                    const uint32_t* Bhf = &bh[nt >> 1][(nt & 1) * 2];
                    const uint32_t* Blf = &bl[nt >> 1][(nt & 1) * 2];
                    mma_bf16(acc[mt][nt], ah[mt], Bhf);
                    mma_bf16(acc[mt][nt], ah[mt], Blf);
                    mma_bf16(acc[mt][nt], al[mt], Bhf);
                }
        }
        buf = (buf == 2) ? 0 : buf + 1;
    }

    // ---- epilogue ----
    int gid = lane >> 2, tig = lane & 3;
    #pragma unroll
    for (int mt = 0; mt < 2; mt++) {
        int r0 = row0 + warp_m * 32 + mt * 16 + gid;
        #pragma unroll
        for (int nt = 0; nt < 8; nt++) {
            int cc = col0 + warp_n * 64 + nt * 8 + tig * 2;
            float2 v0 = make_float2(acc[mt][nt][0], acc[mt][nt][1]);
            float2 v1 = make_float2(acc[mt][nt][2], acc[mt][nt][3]);
            if (mode == 2) {
                float bx = bias[cc], by = bias[cc + 1];
                v0.x = fmaxf(v0.x + bx, 0.f); v0.y = fmaxf(v0.y + by, 0.f);
                v1.x = fmaxf(v1.x + bx, 0.f); v1.y = fmaxf(v1.y + by, 0.f);
                uint32_t h0, l0, h1, l1;
                split2(v0.x, v0.y, h0, l0);
                split2(v1.x, v1.y, h1, l1);
                if (r0 >= M) { h0 = l0 = 0; }
                if (r0 + 8 >= M) { h1 = l1 = 0; }
                *(uint32_t*)&Chi[(size_t)r0 * Nout + cc] = h0;
                *(uint32_t*)&Clo[(size_t)r0 * Nout + cc] = l0;
                *(uint32_t*)&Chi[(size_t)(r0 + 8) * Nout + cc] = h1;
                *(uint32_t*)&Clo[(size_t)(r0 + 8) * Nout + cc] = l1;
            } else {
                if (cc < Nout) {
                    if (r0 < M)     *(float2*)&C[(size_t)r0 * Nout + cc] = v0;
                    if (r0 + 8 < M) *(float2*)&C[(size_t)(r0 + 8) * Nout + cc] = v1;
                }
            }
        }
    }
}

// ---------------------------- launch ---------------------------------------

static inline unsigned blocks_for(size_t total, int threads) {
    return (unsigned)((total + threads - 1) / threads);
}

extern "C" void kernel_launch(void* const* d_in, const int* in_sizes, int n_in,
                              void* d_out, int out_size) {
    const float* x  = (const float*)d_in[0];
    const int*   ei = (const int*)d_in[1];
    const int N = in_sizes[0] / 128;
    const int E = in_sizes[1] / 2;
    const int* src = ei;
    const int* dst = ei + E;
    const float* W1 = (const float*)d_in[2];  const float* b1 = (const float*)d_in[3];
    const float* W2 = (const float*)d_in[4];  const float* b2 = (const float*)d_in[5];
    const float* W3 = (const float*)d_in[6];  const float* b3 = (const float*)d_in[7];
    const float* W4 = (const float*)d_in[8];  const float* b4 = (const float*)d_in[9];
    const float* W5 = (const float*)d_in[10]; const float* b5 = (const float*)d_in[11];
    float* out = (float*)d_out;

    float *bufA, *bufB, *dinv, *csr_nrm;
    int *cnt, *rows, *pos, *partial, *csr_src;
    __nv_bfloat16 *wthi, *wtlo, *ahi, *alo, *bhi, *blo;
    cudaGetSymbolAddress((void**)&bufA, g_bufA);
    cudaGetSymbolAddress((void**)&bufB, g_bufB);
    cudaGetSymbolAddress((void**)&dinv, g_dinv);
    cudaGetSymbolAddress((void**)&cnt, g_cnt);
    cudaGetSymbolAddress((void**)&rows, g_rows);
    cudaGetSymbolAddress((void**)&pos, g_pos);
    cudaGetSymbolAddress((void**)&partial, g_partial);
    cudaGetSymbolAddress((void**)&csr_src, g_csr_src);
    cudaGetSymbolAddress((void**)&csr_nrm, g_csr_nrm);
    cudaGetSymbolAddress((void**)&wthi, g_wthi);
    cudaGetSymbolAddress((void**)&wtlo, g_wtlo);
    cudaGetSymbolAddress((void**)&ahi, g_ahi);
    cudaGetSymbolAddress((void**)&alo, g_alo);
    cudaGetSymbolAddress((void**)&bhi, g_bhi);
    cudaGetSymbolAddress((void**)&blo, g_blo);

    cudaFuncSetAttribute(k_mma_gemm, cudaFuncAttributeMaxDynamicSharedMemorySize,
                         MMA_SMEM);

    const int T = 256;
    const int nblk = (N + 255) / 256;
    const int mtiles = (N + 127) / 128;
    const int Mpad = mtiles * 128;

    // ---- CSR build (cnt pre-zeroed by previous call / static init) ----
    k_hist<<<blocks_for(E, T), T>>>(dst, cnt, E);
    k_scan_blk<<<nblk, T>>>(cnt, rows, partial, dinv, N);
    k_scan_add2<<<nblk, T>>>(rows, pos, partial, cnt, N, E);
    k_scatter<<<blocks_for(E, T), T>>>(src, dst, dinv, pos, csr_src, csr_nrm, E);

    // ---- all weight transposes in one launch ----
    k_wt_all<<<dim3(32, 32, 4), dim3(32, 8)>>>(W1, W2, W3, W4, wthi, wtlo);

    // ---- Layer 1: CSR-agg of x -> ahi/alo [*,128]; GEMM 128->1024
    //      (b1+relu) -> bhi/blo ----
    k_csr_agg_split<32, 0><<<(Mpad + 7) / 8, 256>>>(
        (const float4*)x, rows, csr_src, csr_nrm, dinv, nullptr,
        (uint2*)ahi, (uint2*)alo, N, Mpad);
    k_mma_gemm<<<dim3(1024 / 128, mtiles), 256, MMA_SMEM>>>(
        ahi, alo, wthi + WOFF1, wtlo + WOFF1, b1, nullptr, bhi, blo,
        N, 128, 1024, 2);

    // ---- Layer 2: GEMM 1024->512 -> bufA; CSR-agg (+b2, relu) -> ahi/alo ----
    k_mma_gemm<<<dim3(512 / 128, mtiles), 256, MMA_SMEM>>>(
        bhi, blo, wthi + WOFF2, wtlo + WOFF2, nullptr, bufA, nullptr, nullptr,
        N, 1024, 512, 0);
    k_csr_agg_split<128, 1><<<(Mpad + 1) / 2, 256>>>(
        (const float4*)bufA, rows, csr_src, csr_nrm, dinv, b2,
        (uint2*)ahi, (uint2*)alo, N, Mpad);

    // ---- Layer 3: GEMM 512->256 -> bufA; CSR-agg (+b3, relu) -> ahi/alo ----
    k_mma_gemm<<<dim3(256 / 128, mtiles), 256, MMA_SMEM>>>(
        ahi, alo, wthi + WOFF3, wtlo + WOFF3, nullptr, bufA, nullptr, nullptr,
        N, 512, 256, 0);
    k_csr_agg_split<64, 1><<<(Mpad + 3) / 4, 256>>>(
        (const float4*)bufA, rows, csr_src, csr_nrm, dinv, b3,
        (uint2*)ahi, (uint2*)alo, N, Mpad);

    // ---- Layer 4: GEMM 256->64 (weights padded to 128 cols) -> bufA;
    //      fused CSR-agg (+b4) + relu + W5 matvec -> bufB (mv) ----
    k_mma_gemm<<<dim3(1, mtiles), 256, MMA_SMEM>>>(
        ahi, alo, wthi + WOFF4, wtlo + WOFF4, nullptr, bufA, nullptr, nullptr,
        N, 256, 64, 0);
    k_csr_agg_mv<<<(N + 15) / 16, 256>>>(
        (const float4*)bufA, rows, csr_src, csr_nrm, dinv, b4, W5, bufB, N);

    // ---- Layer 5 tail: scalar CSR-agg into out ----
    k_out_scalar<<<nblk, T>>>(bufB, rows, csr_src, csr_nrm, dinv, b5, out, N);
}

// round 14
// speedup vs baseline: 1.0352x; 1.0089x over previous
#include <cuda_runtime.h>
#include <cuda_bf16.h>
#include <cstddef>
#include <cstdint>

// ---------------------------------------------------------------------------
// ConvGraphNet (5-layer GCN) on GB300.
// R14: mma.sync bf16x3 GEMMs with BN=256 block tiles (halves A-operand
//      re-read traffic for L1-L3); L4 on 128-wide 3-stage path.
//      CSR build 4 launches; L5 matvec fused into L4 agg.
// ---------------------------------------------------------------------------

#define NODES_MAX 50000
#define EDGES_MAX 400000
#define MPAD_MAX  50048   // 391 * 128

static __device__ float g_bufA[(size_t)NODES_MAX * 1024];
static __device__ float g_bufB[(size_t)NODES_MAX * 1024];
static __device__ float g_dinv[NODES_MAX];
static __device__ int   g_cnt[NODES_MAX];
static __device__ int   g_rows[NODES_MAX + 1];
static __device__ int   g_pos[NODES_MAX];
static __device__ int   g_partial[256];
static __device__ int   g_csr_src[EDGES_MAX];
static __device__ float g_csr_nrm[EDGES_MAX];
static __device__ __nv_bfloat16 g_wthi[1 << 20];
static __device__ __nv_bfloat16 g_wtlo[1 << 20];
static __device__ __nv_bfloat16 g_ahi[(size_t)MPAD_MAX * 512];
static __device__ __nv_bfloat16 g_alo[(size_t)MPAD_MAX * 512];
static __device__ __nv_bfloat16 g_bhi[(size_t)MPAD_MAX * 1024];
static __device__ __nv_bfloat16 g_blo[(size_t)MPAD_MAX * 1024];

// weight-transpose regions inside g_wthi/g_wtlo
#define WOFF1 0          // W1t: 1024 x 128
#define WOFF2 131072     // W2t: 512 x 1024
#define WOFF3 655360     // W3t: 256 x 512
#define WOFF4 786432     // W4t: 128 x 256 (cols 64..127 zero)

// ---------------------------- PTX helpers ----------------------------------

__device__ __forceinline__ uint32_t smem_u32(const void* p) {
    uint32_t a;
    asm("{ .reg .u64 t; cvta.to.shared.u64 t, %1; cvt.u32.u64 %0, t; }"
        : "=r"(a) : "l"(p));
    return a;
}

__device__ __forceinline__ void cpa16(uint32_t s, const void* g) {
    asm volatile("cp.async.cg.shared.global [%0], [%1], 16;" :: "r"(s), "l"(g));
}

__device__ __forceinline__ void ldsm_x4(uint32_t* r, uint32_t addr) {
    asm volatile("ldmatrix.sync.aligned.m8n8.x4.shared.b16 {%0,%1,%2,%3}, [%4];"
                 : "=r"(r[0]), "=r"(r[1]), "=r"(r[2]), "=r"(r[3]) : "r"(addr));
}

__device__ __forceinline__ void mma_bf16(float* d, const uint32_t* a, const uint32_t* b) {
    asm volatile("mma.sync.aligned.m16n8k16.row.col.f32.bf16.bf16.f32 "
                 "{%0,%1,%2,%3}, {%4,%5,%6,%7}, {%8,%9}, {%0,%1,%2,%3};"
                 : "+f"(d[0]), "+f"(d[1]), "+f"(d[2]), "+f"(d[3])
                 : "r"(a[0]), "r"(a[1]), "r"(a[2]), "r"(a[3]), "r"(b[0]), "r"(b[1]));
}

__device__ __forceinline__ void split2(float x, float y, uint32_t& h, uint32_t& l) {
    __nv_bfloat162 hb = __floats2bfloat162_rn(x, y);
    float2 hf = __bfloat1622float2(hb);
    __nv_bfloat162 lb = __floats2bfloat162_rn(x - hf.x, y - hf.y);
    h = *(uint32_t*)&hb;
    l = *(uint32_t*)&lb;
}

// ---------------------------- CSR build ------------------------------------

__global__ void k_hist(const int* __restrict__ dst, int* __restrict__ cnt, int e) {
    int i = blockIdx.x * blockDim.x + threadIdx.x;
    if (i < e) atomicAdd(&cnt[dst[i]], 1);
}

__global__ void k_scan_blk(const int* __restrict__ cnt, int* __restrict__ rows,
                           int* __restrict__ partial, float* __restrict__ dinv, int n) {
    __shared__ int sm[256];
    int t = threadIdx.x;
    int i = blockIdx.x * 256 + t;
    int v = (i < n) ? cnt[i] : 0;
    if (i < n) dinv[i] = rsqrtf((float)(v + 1));
    sm[t] = v;
    __syncthreads();
    #pragma unroll
    for (int off = 1; off < 256; off <<= 1) {
        int x = (t >= off) ? sm[t - off] : 0;
        __syncthreads();
        sm[t] += x;
        __syncthreads();
    }
    if (i < n) rows[i] = sm[t] - v;
    if (t == 255) partial[blockIdx.x] = sm[255];
}

__global__ void k_scan_add2(int* __restrict__ rows, int* __restrict__ pos,
                            const int* __restrict__ partial, int* __restrict__ cnt,
                            int n, int e_total) {
    __shared__ int sm[256];
    int t = threadIdx.x;
    int bid = blockIdx.x;
    sm[t] = (t < bid) ? partial[t] : 0;
    __syncthreads();
    #pragma unroll
    for (int off = 128; off >= 1; off >>= 1) {
        if (t < off) sm[t] += sm[t + off];
        __syncthreads();
    }
    int offv = sm[0];
    int i = bid * 256 + t;
    if (i < n) {
        int r = rows[i] + offv;
        rows[i] = r;
        pos[i] = r;
        cnt[i] = 0;
    }
    if (i == 0) rows[n] = e_total;
}

__global__ void k_scatter(const int* __restrict__ src, const int* __restrict__ dst,
                          const float* __restrict__ dinv, int* __restrict__ pos,
                          int* __restrict__ csr_src, float* __restrict__ csr_nrm, int e) {
    int i = blockIdx.x * blockDim.x + threadIdx.x;
    if (i >= e) return;
    int s = src[i], d = dst[i];
    int j = atomicAdd(&pos[d], 1);
    csr_src[j] = s;
    csr_nrm[j] = dinv[s] * dinv[d];
}

// ---------------------------- CSR aggregation -------------------------------

template <int F4PN, int RELU>
__global__ __launch_bounds__(256)
void k_csr_agg_split(const float4* __restrict__ X, const int* __restrict__ rows,
                     const int* __restrict__ csr_src, const float* __restrict__ csr_nrm,
                     const float* __restrict__ dinv, const float* __restrict__ bias,
                     uint2* __restrict__ hi, uint2* __restrict__ lo, int n, int npad) {
    const int NPB = 256 / F4PN;
    int tid = threadIdx.x;
    int local = tid / F4PN;
    int f4 = tid % F4PN;
    int i = blockIdx.x * NPB + local;
    if (i >= npad) return;
    size_t base = (size_t)i * F4PN + f4;
    if (i >= n) {
        hi[base] = make_uint2(0, 0);
        lo[base] = make_uint2(0, 0);
        return;
    }

    float d = dinv[i];
    float s = d * d;
    float4 xs = X[base];
    float4 acc;
    acc.x = xs.x * s; acc.y = xs.y * s; acc.z = xs.z * s; acc.w = xs.w * s;
    if (bias) {
        float4 b = ((const float4*)bias)[f4];
        acc.x += b.x; acc.y += b.y; acc.z += b.z; acc.w += b.w;
    }
    int beg = rows[i], end = rows[i + 1];
    for (int j = beg; j < end; j++) {
        float w = csr_nrm[j];
        float4 v = X[(size_t)csr_src[j] * F4PN + f4];
        acc.x = fmaf(w, v.x, acc.x);
        acc.y = fmaf(w, v.y, acc.y);
        acc.z = fmaf(w, v.z, acc.z);
        acc.w = fmaf(w, v.w, acc.w);
    }
    if (RELU) {
        acc.x = fmaxf(acc.x, 0.f); acc.y = fmaxf(acc.y, 0.f);
        acc.z = fmaxf(acc.z, 0.f); acc.w = fmaxf(acc.w, 0.f);
    }
    uint2 uh, ul;
    split2(acc.x, acc.y, uh.x, ul.x);
    split2(acc.z, acc.w, uh.y, ul.y);
    hi[base] = uh;
    lo[base] = ul;
}

// L4 aggregation (F=64, +b4) fused with relu + W5 matvec -> mv[i].
__global__ __launch_bounds__(256)
void k_csr_agg_mv(const float4* __restrict__ X, const int* __restrict__ rows,
                  const int* __restrict__ csr_src, const float* __restrict__ csr_nrm,
                  const float* __restrict__ dinv, const float* __restrict__ b4,
                  const float* __restrict__ W5, float* __restrict__ mv, int n) {
    int tid = threadIdx.x;
    int local = tid >> 4;
    int f4 = tid & 15;
    int i = blockIdx.x * 16 + local;
    bool valid = (i < n);
    int ii = valid ? i : 0;

    float d = dinv[ii];
    float s = d * d;
    size_t base = (size_t)ii * 16 + f4;
    float4 xs = X[base];
    float4 b = ((const float4*)b4)[f4];
    float4 acc;
    acc.x = fmaf(xs.x, s, b.x); acc.y = fmaf(xs.y, s, b.y);
    acc.z = fmaf(xs.z, s, b.z); acc.w = fmaf(xs.w, s, b.w);
    int beg = rows[ii], end = valid ? rows[ii + 1] : rows[ii];
    for (int j = beg; j < end; j++) {
        float w = csr_nrm[j];
        float4 v = X[(size_t)csr_src[j] * 16 + f4];
        acc.x = fmaf(w, v.x, acc.x);
        acc.y = fmaf(w, v.y, acc.y);
        acc.z = fmaf(w, v.z, acc.z);
        acc.w = fmaf(w, v.w, acc.w);
    }
    float4 w5 = ((const float4*)W5)[f4];
    float p = fmaxf(acc.x, 0.f) * w5.x + fmaxf(acc.y, 0.f) * w5.y +
              fmaxf(acc.z, 0.f) * w5.z + fmaxf(acc.w, 0.f) * w5.w;
    p += __shfl_xor_sync(0xffffffffu, p, 8, 16);
    p += __shfl_xor_sync(0xffffffffu, p, 4, 16);
    p += __shfl_xor_sync(0xffffffffu, p, 2, 16);
    p += __shfl_xor_sync(0xffffffffu, p, 1, 16);
    if (valid && f4 == 0) mv[i] = p;
}

__global__ void k_out_scalar(const float* __restrict__ mv, const int* __restrict__ rows,
                             const int* __restrict__ csr_src, const float* __restrict__ csr_nrm,
                             const float* __restrict__ dinv, const float* __restrict__ b5,
                             float* __restrict__ out, int n) {
    int i = blockIdx.x * blockDim.x + threadIdx.x;
    if (i >= n) return;
    float d = dinv[i];
    float s = b5[0] + d * d * mv[i];
    int beg = rows[i], end = rows[i + 1];
    for (int j = beg; j < end; j++)
        s = fmaf(csr_nrm[j], mv[csr_src[j]], s);
    out[i] = fmaxf(s, 0.0f);
}

// ---------------- batched tiled weight transpose + bf16 split ---------------

__global__ __launch_bounds__(256)
void k_wt_all(const float* __restrict__ W1, const float* __restrict__ W2,
              const float* __restrict__ W3, const float* __restrict__ W4,
              __nv_bfloat16* __restrict__ hi, __nv_bfloat16* __restrict__ lo) {
    __shared__ float tile[32][33];
    const float* W;
    int K, Nv, Npad;
    size_t off;
    switch (blockIdx.z) {
        case 0:  W = W1; K = 128;  Nv = 1024; Npad = 1024; off = WOFF1; break;
        case 1:  W = W2; K = 1024; Nv = 512;  Npad = 512;  off = WOFF2; break;
        case 2:  W = W3; K = 512;  Nv = 256;  Npad = 256;  off = WOFF3; break;
        default: W = W4; K = 256;  Nv = 64;   Npad = 128;  off = WOFF4; break;
    }
    int k0 = blockIdx.x * 32;
    int n0 = blockIdx.y * 32;
    if (k0 >= K || n0 >= Npad) return;
    int tx = threadIdx.x, ty = threadIdx.y;
    #pragma unroll
    for (int i = ty; i < 32; i += 8) {
        int k = k0 + i, n = n0 + tx;
        tile[i][tx] = (n < Nv) ? W[(size_t)k * Nv + n] : 0.0f;
    }
    __syncthreads();
    #pragma unroll
    for (int i = ty; i < 32; i += 8) {
        int n = n0 + i, k = k0 + tx;
        float v = tile[tx][i];
        __nv_bfloat16 h = __float2bfloat16(v);
        hi[off + (size_t)n * K + k] = h;
        lo[off + (size_t)n * K + k] = __float2bfloat16(v - __bfloat162float(h));
    }
}

// ---------------------- mma.sync bf16x3 GEMM --------------------------------
// Template: BROWS = B rows per block tile (column-tile width 128 or 256),
// NST = pipeline stages. Block 128 x BROWS, 8 warps (4m x 2n),
// warp tile 32 x (BROWS/2). A bf16 hi/lo [Mpad,K]; W bf16 hi/lo K-major.
// mode 0: fp32 out (stride Nout, cols < Nout). mode 2: bf16 hi/lo out
// (bias+relu), pad rows zeroed.

#define SROW 144
#define MMA_SMEM 221184

template <int BROWS, int NST>
__global__ __launch_bounds__(256, 1)
void k_mma_gemm(const __nv_bfloat16* __restrict__ Ah, const __nv_bfloat16* __restrict__ Al,
                const __nv_bfloat16* __restrict__ Bh, const __nv_bfloat16* __restrict__ Bl,
                const float* __restrict__ bias, float* __restrict__ C,
                __nv_bfloat16* __restrict__ Chi, __nv_bfloat16* __restrict__ Clo,
                int M, int K, int Nout, int mode) {
    extern __shared__ char smem[];
    const uint32_t sb = smem_u32(smem);
    const int tid = threadIdx.x;
    const int wid = tid >> 5;
    const int lane = tid & 31;
    const int warp_m = wid & 3;
    const int warp_n = wid >> 2;
    const int row0 = blockIdx.y * 128;
    const int col0 = blockIdx.x * BROWS;
    const int nc = K >> 6;

    const int NT = BROWS / 16;           // n-tiles per warp (8 or 16)
    const int HALVES = BROWS / 128;      // 64-col fragment groups (1 or 2)
    const uint32_t offAh = 0;
    const uint32_t offAl = 128 * SROW;
    const uint32_t offBh = 2 * 128 * SROW;
    const uint32_t offBl = 2 * 128 * SROW + BROWS * SROW;
    const uint32_t STAGE = 2 * 128 * SROW + 2 * BROWS * SROW;

    float acc[2][NT][4];
    #pragma unroll
    for (int i = 0; i < 2; i++)
        #pragma unroll
        for (int j = 0; j < NT; j++)
            #pragma unroll
            for (int c = 0; c < 4; c++) acc[i][j][c] = 0.0f;

    auto issue = [&](int t, int q) {
        size_t k0 = (size_t)t << 6;
        uint32_t st = sb + q * STAGE;
        #pragma unroll
        for (int l = 0; l < 4; l++) {      // A: 128 rows * 8 chunks / 256
            int idx = tid + l * 256;
            int r = idx >> 3;
            int c = idx & 7;
            uint32_t o = (uint32_t)(r * SROW + c * 16);
            size_t ga = (size_t)(row0 + r) * K + k0 + c * 8;
            cpa16(st + offAh + o, Ah + ga);
            cpa16(st + offAl + o, Al + ga);
        }
        #pragma unroll
        for (int l = 0; l < BROWS / 32; l++) {  // B: BROWS rows * 8 / 256
            int idx = tid + l * 256;
            int r = idx >> 3;
            int c = idx & 7;
            uint32_t o = (uint32_t)(r * SROW + c * 16);
            size_t gb = (size_t)(col0 + r) * K + k0 + c * 8;
            cpa16(st + offBh + o, Bh + gb);
            cpa16(st + offBl + o, Bl + gb);
        }
        asm volatile("cp.async.commit_group;" ::: "memory");
    };

    issue(0, 0);
    if (NST > 2 && nc > 1) issue(1, 1);

    int buf = 0;
    for (int t = 0; t < nc; t++) {
        if (NST > 2 && t + 1 < nc) {
            asm volatile("cp.async.wait_group 1;" ::: "memory");
        } else {
            asm volatile("cp.async.wait_group 0;" ::: "memory");
        }
        __syncthreads();
        if (t + NST - 1 < nc) issue(t + NST - 1, (t + NST - 1) % NST);

        uint32_t st = sb + buf * STAGE;
        #pragma unroll
        for (int ks = 0; ks < 4; ks++) {
            uint32_t ah[2][4], al[2][4];
            {
                uint32_t rr = (uint32_t)(warp_m * 32 + (lane & 15));
                uint32_t cc = (uint32_t)(ks * 16 + ((lane >> 4) << 3));
                #pragma unroll
                for (int mt = 0; mt < 2; mt++) {
                    uint32_t o = (rr + mt * 16) * SROW + cc * 2;
                    ldsm_x4(ah[mt], st + offAh + o);
                    ldsm_x4(al[mt], st + offAl + o);
                }
            }
            #pragma unroll
            for (int half = 0; half < HALVES; half++) {
                uint32_t bh[4][4], bl[4][4];
                {
                    int j = lane >> 3;
                    uint32_t nn = (uint32_t)(warp_n * (BROWS / 2) + half * 64 +
                                             ((j >> 1) << 3) + (lane & 7));
                    uint32_t kk = (uint32_t)(ks * 16 + ((j & 1) << 3));
                    #pragma unroll
                    for (int pp = 0; pp < 4; pp++) {
                        uint32_t o = (nn + pp * 16) * SROW + kk * 2;
                        ldsm_x4(bh[pp], st + offBh + o);
                        ldsm_x4(bl[pp], st + offBl + o);
                    }
                }
                #pragma unroll
                for (int mt = 0; mt < 2; mt++)
                    #pragma unroll
                    for (int ntl = 0; ntl < 8; ntl++) {
                        int nt = half * 8 + ntl;
                        const uint32_t* Bhf = &bh[ntl >> 1][(ntl & 1) * 2];
                        const uint32_t* Blf = &bl[ntl >> 1][(ntl & 1) * 2];
                        mma_bf16(acc[mt][nt], ah[mt], Bhf);
                        mma_bf16(acc[mt][nt], ah[mt], Blf);
                        mma_bf16(acc[mt][nt], al[mt], Bhf);
                    }
            }
        }
        buf = (buf + 1 == NST) ? 0 : buf + 1;
    }

    // ---- epilogue ----
    int gid = lane >> 2, tig = lane & 3;
    #pragma unroll
    for (int mt = 0; mt < 2; mt++) {
        int r0 = row0 + warp_m * 32 + mt * 16 + gid;
        #pragma unroll
        for (int nt = 0; nt < NT; nt++) {
            int cc = col0 + warp_n * (BROWS / 2) + nt * 8 + tig * 2;
            float2 v0 = make_float2(acc[mt][nt][0], acc[mt][nt][1]);
            float2 v1 = make_float2(acc[mt][nt][2], acc[mt][nt][3]);
            if (mode == 2) {
                float bx = bias[cc], by = bias[cc + 1];
                v0.x = fmaxf(v0.x + bx, 0.f); v0.y = fmaxf(v0.y + by, 0.f);
                v1.x = fmaxf(v1.x + bx, 0.f); v1.y = fmaxf(v1.y + by, 0.f);
                uint32_t h0, l0, h1, l1;
                split2(v0.x, v0.y, h0, l0);
                split2(v1.x, v1.y, h1, l1);
                if (r0 >= M) { h0 = l0 = 0; }
                if (r0 + 8 >= M) { h1 = l1 = 0; }
                *(uint32_t*)&Chi[(size_t)r0 * Nout + cc] = h0;
                *(uint32_t*)&Clo[(size_t)r0 * Nout + cc] = l0;
                *(uint32_t*)&Chi[(size_t)(r0 + 8) * Nout + cc] = h1;
                *(uint32_t*)&Clo[(size_t)(r0 + 8) * Nout + cc] = l1;
            } else {
                if (cc < Nout) {
                    if (r0 < M)     *(float2*)&C[(size_t)r0 * Nout + cc] = v0;
                    if (r0 + 8 < M) *(float2*)&C[(size_t)(r0 + 8) * Nout + cc] = v1;
                }
            }
        }
    }
}

// ---------------------------- launch ---------------------------------------

static inline unsigned blocks_for(size_t total, int threads) {
    return (unsigned)((total + threads - 1) / threads);
}

extern "C" void kernel_launch(void* const* d_in, const int* in_sizes, int n_in,
                              void* d_out, int out_size) {
    const float* x  = (const float*)d_in[0];
    const int*   ei = (const int*)d_in[1];
    const int N = in_sizes[0] / 128;
    const int E = in_sizes[1] / 2;
    const int* src = ei;
    const int* dst = ei + E;
    const float* W1 = (const float*)d_in[2];  const float* b1 = (const float*)d_in[3];
    const float* W2 = (const float*)d_in[4];  const float* b2 = (const float*)d_in[5];
    const float* W3 = (const float*)d_in[6];  const float* b3 = (const float*)d_in[7];
    const float* W4 = (const float*)d_in[8];  const float* b4 = (const float*)d_in[9];
    const float* W5 = (const float*)d_in[10]; const float* b5 = (const float*)d_in[11];
    float* out = (float*)d_out;

    float *bufA, *bufB, *dinv, *csr_nrm;
    int *cnt, *rows, *pos, *partial, *csr_src;
    __nv_bfloat16 *wthi, *wtlo, *ahi, *alo, *bhi, *blo;
    cudaGetSymbolAddress((void**)&bufA, g_bufA);
    cudaGetSymbolAddress((void**)&bufB, g_bufB);
    cudaGetSymbolAddress((void**)&dinv, g_dinv);
    cudaGetSymbolAddress((void**)&cnt, g_cnt);
    cudaGetSymbolAddress((void**)&rows, g_rows);
    cudaGetSymbolAddress((void**)&pos, g_pos);
    cudaGetSymbolAddress((void**)&partial, g_partial);
    cudaGetSymbolAddress((void**)&csr_src, g_csr_src);
    cudaGetSymbolAddress((void**)&csr_nrm, g_csr_nrm);
    cudaGetSymbolAddress((void**)&wthi, g_wthi);
    cudaGetSymbolAddress((void**)&wtlo, g_wtlo);
    cudaGetSymbolAddress((void**)&ahi, g_ahi);
    cudaGetSymbolAddress((void**)&alo, g_alo);
    cudaGetSymbolAddress((void**)&bhi, g_bhi);
    cudaGetSymbolAddress((void**)&blo, g_blo);

    cudaFuncSetAttribute(k_mma_gemm<256, 2>,
                         cudaFuncAttributeMaxDynamicSharedMemorySize, MMA_SMEM);
    cudaFuncSetAttribute(k_mma_gemm<128, 3>,
                         cudaFuncAttributeMaxDynamicSharedMemorySize, MMA_SMEM);

    const int T = 256;
    const int nblk = (N + 255) / 256;
    const int mtiles = (N + 127) / 128;
    const int Mpad = mtiles * 128;

    // ---- CSR build (cnt pre-zeroed by previous call / static init) ----
    k_hist<<<blocks_for(E, T), T>>>(dst, cnt, E);
    k_scan_blk<<<nblk, T>>>(cnt, rows, partial, dinv, N);
    k_scan_add2<<<nblk, T>>>(rows, pos, partial, cnt, N, E);
    k_scatter<<<blocks_for(E, T), T>>>(src, dst, dinv, pos, csr_src, csr_nrm, E);

    // ---- weight transposes (one launch) ----
    k_wt_all<<<dim3(32, 32, 4), dim3(32, 8)>>>(W1, W2, W3, W4, wthi, wtlo);

    // ---- Layer 1: CSR-agg of x -> ahi/alo [*,128]; GEMM 128->1024
    //      (b1+relu) -> bhi/blo ----
    k_csr_agg_split<32, 0><<<(Mpad + 7) / 8, 256>>>(
        (const float4*)x, rows, csr_src, csr_nrm, dinv, nullptr,
        (uint2*)ahi, (uint2*)alo, N, Mpad);
    k_mma_gemm<256, 2><<<dim3(1024 / 256, mtiles), 256, MMA_SMEM>>>(
        ahi, alo, wthi + WOFF1, wtlo + WOFF1, b1, nullptr, bhi, blo,
        N, 128, 1024, 2);

    // ---- Layer 2: GEMM 1024->512 -> bufA; CSR-agg (+b2, relu) -> ahi/alo ----
    k_mma_gemm<256, 2><<<dim3(512 / 256, mtiles), 256, MMA_SMEM>>>(
        bhi, blo, wthi + WOFF2, wtlo + WOFF2, nullptr, bufA, nullptr, nullptr,
        N, 1024, 512, 0);
    k_csr_agg_split<128, 1><<<(Mpad + 1) / 2, 256>>>(
        (const float4*)bufA, rows, csr_src, csr_nrm, dinv, b2,
        (uint2*)ahi, (uint2*)alo, N, Mpad);

    // ---- Layer 3: GEMM 512->256 -> bufA; CSR-agg (+b3, relu) -> ahi/alo ----
    k_mma_gemm<256, 2><<<dim3(1, mtiles), 256, MMA_SMEM>>>(
        ahi, alo, wthi + WOFF3, wtlo + WOFF3, nullptr, bufA, nullptr, nullptr,
        N, 512, 256, 0);
    k_csr_agg_split<64, 1><<<(Mpad + 3) / 4, 256>>>(
        (const float4*)bufA, rows, csr_src, csr_nrm, dinv, b3,
        (uint2*)ahi, (uint2*)alo, N, Mpad);

    // ---- Layer 4: GEMM 256->64 (weights padded to 128 cols) -> bufA;
    //      fused CSR-agg (+b4) + relu + W5 matvec -> bufB (mv) ----
    k_mma_gemm<128, 3><<<dim3(1, mtiles), 256, MMA_SMEM>>>(
        ahi, alo, wthi + WOFF4, wtlo + WOFF4, nullptr, bufA, nullptr, nullptr,
        N, 256, 64, 0);
    k_csr_agg_mv<<<(N + 15) / 16, 256>>>(
        (const float4*)bufA, rows, csr_src, csr_nrm, dinv, b4, W5, bufB, N);

    // ---- Layer 5 tail: scalar CSR-agg into out ----
    k_out_scalar<<<nblk, T>>>(bufB, rows, csr_src, csr_nrm, dinv, b5, out, N);
}